// round 3
// baseline (speedup 1.0000x reference)
#include <cuda_runtime.h>
#include <cstdint>

// Problem constants (from reference)
constexpr int Bn  = 64;      // batch
constexpr int Cc  = 32;      // preds per sample
constexpr int Pp  = 5;       // pred param dim
constexpr int TDd = 8;       // target param dim (use [3:8])
constexpr int NTt = 32;      // targets per sample
constexpr int NHh = 32768;   // hits
constexpr int SCc = 16;      // seg classes
constexpr int NCc = 3;       // pred classes

constexpr int SEG_BLOCKS = 2048;
constexpr int THREADS    = 256;
constexpr long long TOTAL_ROWS = (long long)Bn * NHh;  // 2,097,152

#define FULL 0xffffffffu

// Scratch (no device allocation allowed)
__device__ double g_seg_partial[SEG_BLOCKS];
__device__ float  g_hung[Bn];
__device__ int    g_adj[Bn * Cc];

// ---- int32 / int64 input detection -----------------------------------------
// If the ints are true little-endian int64 (values in [0,16)), every odd 32-bit
// word of the first 32 elements is 0. With int32 data those words are iid
// uniform in [0,16): P(all 32 zero) = 16^-32.
__device__ __forceinline__ bool detect_int64(const void* hit_labels)
{
    const int* w = (const int*)hit_labels;
    int acc = 0;
    #pragma unroll
    for (int i = 0; i < 32; i++) acc |= w[2 * i + 1];
    return acc == 0;
}

__device__ __forceinline__ int geti(const void* p, long long i, bool i64)
{
    return i64 ? (int)((const long long*)p)[i] : ((const int*)p)[i];
}

__global__ void __launch_bounds__(THREADS)
fused_kernel(const float* __restrict__ pred_params,
             const float* __restrict__ hit_logits,
             const float* __restrict__ target_params,
             const void*  __restrict__ target_labels,
             const void*  __restrict__ hit_labels,
             const void*  __restrict__ preds_lengths,
             const void*  __restrict__ targets_lengths)
{
    const int tid = threadIdx.x;
    const bool i64 = detect_int64(hit_labels);

    if (blockIdx.x < (unsigned)Bn) {
        // ====== Matching: replicate the reference's _lsa EXACTLY =================
        // The reference's minv/way updates are computed on copies and never
        // written back, so effectively: minv stays INF (each inner step is a
        // fresh argmin of cost[i0-1,:] - u[i0] - v over unused columns) and
        // way stays 0 (the "augmentation" assigns row i to the final free
        // column in one step; intermediate matches are untouched).
        const int b = blockIdx.x;
        __shared__ double cost[32 * 33];
        __shared__ double u_sh[33];

        const int n0 = geti(preds_lengths, b, i64);
        const int m0 = geti(targets_lengths, b, i64);
        const bool transposed = n0 > m0;   // reference transposes so rows <= cols
        const int n = transposed ? m0 : n0;
        const int m = transposed ? n0 : m0;

        const float* pp = pred_params   + (size_t)b * Cc * Pp;
        const float* tp = target_params + (size_t)b * NTt * TDd;

        // Fill full 32x32 cost in f64 (sequential 5-term sum, matches numpy)
        for (int idx = tid; idx < 32 * 32; idx += THREADS) {
            const int r = idx >> 5, c = idx & 31;
            const int pi = transposed ? c : r;
            const int ti = transposed ? r : c;
            double s = 0.0;
            #pragma unroll
            for (int d = 0; d < Pp; d++)
                s += fabs((double)pp[pi * Pp + d] - (double)tp[ti * TDd + 3 + d]);
            cost[r * 33 + c] = s;
        }
        if (tid < 33) u_sh[tid] = 0.0;
        __syncthreads();
        if (tid >= 32) return;          // warp 0 only from here

        const int lane = tid;
        const double INF = 1e300;
        double v = 0.0;                 // column potential; lane owns column lane+1
        int p = 0;                      // row matched to this column (0 = none)

        for (int i = 1; i <= n; i++) {
            bool used = false;
            int j0 = 0;
            while (true) {
                if (j0 > 0 && lane == j0 - 1) used = true;
                const int i0 = (j0 == 0) ? i : __shfl_sync(FULL, p, j0 - 1);
                const double ui0 = u_sh[i0];
                // fresh min each step (minv is never persisted in the reference)
                double val = (lane < m && !used)
                           ? (cost[(i0 - 1) * 33 + lane] - ui0 - v) : INF;
                int idx = lane;
                #pragma unroll
                for (int off = 16; off; off >>= 1) {
                    const double ov = __shfl_xor_sync(FULL, val, off);
                    const int    oi = __shfl_xor_sync(FULL, idx, off);
                    if (ov < val || (ov == val && oi < idx)) { val = ov; idx = oi; }
                }
                const double delta = val;
                const int j1 = idx + 1;

                if (lane == 0) u_sh[i] += delta;      // u[p[0]] = u[i] += delta
                if (used) {                            // u[p[used]] += delta
                    u_sh[p] += delta;                  // distinct rows: no race
                    v -= delta;                        // v[used]   -= delta
                }
                __syncwarp();
                j0 = j1;
                const int pj0 = __shfl_sync(FULL, p, j0 - 1);
                if (pj0 == 0) break;
            }
            // way[] is all zeros in the reference -> single-step assignment
            if (lane == j0 - 1) p = i;
            __syncwarp();
        }

        // matched pairs: lane < m with p != 0 : alg_row = p-1, alg_col = lane
        const bool matched = (lane < m) && (p != 0);
        int pred_i = 0, tgt_i = 0;
        float l1 = 0.0f;
        if (matched) {
            pred_i = transposed ? lane : (p - 1);
            tgt_i  = transposed ? (p - 1) : lane;
            float s = 0.0f;
            #pragma unroll
            for (int d = 0; d < Pp; d++)
                s += fabsf(pp[pred_i * Pp + d] - tp[tgt_i * TDd + 3 + d]);
            l1 = s;
        }
        float tot = l1;
        #pragma unroll
        for (int off = 16; off; off >>= 1) tot += __shfl_xor_sync(FULL, tot, off);
        if (lane == 0) g_hung[b] = tot / (float)(n * Pp);

        g_adj[b * Cc + lane] = 1;                     // default class = 1
        __syncwarp();
        if (matched)
            g_adj[b * Cc + pred_i] = geti(target_labels, (long long)b * NTt + tgt_i, i64);
    } else {
        // ================= Segmentation loss scan (HBM-bound) =====================
        const int sb = blockIdx.x - Bn;
        float acc = 0.0f;
        for (long long row = (long long)sb * THREADS + tid; row < TOTAL_ROWS;
             row += (long long)SEG_BLOCKS * THREADS) {
            const float4* p4 = (const float4*)(hit_logits + row * SCc);
            const float4 a = p4[0], b4 = p4[1], c = p4[2], d = p4[3];
            float mx = fmaxf(fmaxf(fmaxf(a.x, a.y), fmaxf(a.z, a.w)),
                             fmaxf(fmaxf(b4.x, b4.y), fmaxf(b4.z, b4.w)));
            mx = fmaxf(mx, fmaxf(fmaxf(c.x, c.y), fmaxf(c.z, c.w)));
            mx = fmaxf(mx, fmaxf(fmaxf(d.x, d.y), fmaxf(d.z, d.w)));
            float s = __expf(a.x - mx) + __expf(a.y - mx) + __expf(a.z - mx) + __expf(a.w - mx)
                    + __expf(b4.x - mx) + __expf(b4.y - mx) + __expf(b4.z - mx) + __expf(b4.w - mx)
                    + __expf(c.x - mx) + __expf(c.y - mx) + __expf(c.z - mx) + __expf(c.w - mx)
                    + __expf(d.x - mx) + __expf(d.y - mx) + __expf(d.z - mx) + __expf(d.w - mx);
            const int lab = geti(hit_labels, row, i64);
            const float xl = hit_logits[row * SCc + lab];   // L1 hit (line just loaded)
            acc += (mx + __logf(s)) - xl;
        }
        __shared__ float red[THREADS];
        red[tid] = acc;
        __syncthreads();
        #pragma unroll
        for (int off = THREADS / 2; off; off >>= 1) {
            if (tid < off) red[tid] += red[tid + off];
            __syncthreads();
        }
        if (tid == 0) g_seg_partial[sb] = (double)red[0];
    }
}

__global__ void __launch_bounds__(THREADS)
final_kernel(const float* __restrict__ pred_logits,
             const float* __restrict__ vertex,
             const float* __restrict__ target_params,
             float* __restrict__ out)
{
    const int tid = threadIdx.x;
    double seg = 0.0, lab = 0.0, vx = 0.0, hg = 0.0;

    for (int i = tid; i < SEG_BLOCKS; i += THREADS) seg += g_seg_partial[i];
    for (int i = tid; i < Bn; i += THREADS)         hg  += (double)g_hung[i];

    for (int r = tid; r < Bn * Cc; r += THREADS) {
        const float* x = pred_logits + (size_t)r * NCc;
        const float x0 = x[0], x1 = x[1], x2 = x[2];
        const float mx = fmaxf(x0, fmaxf(x1, x2));
        const float s = __expf(x0 - mx) + __expf(x1 - mx) + __expf(x2 - mx);
        const int a = g_adj[r];
        const float xa = (a == 0) ? x0 : ((a == 1) ? x1 : x2);
        lab += (double)((mx + __logf(s)) - xa);
    }
    for (int e = tid; e < Bn * 3; e += THREADS) {
        const int bi = e / 3, d = e % 3;
        const float w = (d == 2) ? 0.8f : 0.1f;
        vx += (double)fabsf(vertex[e] * w - target_params[(size_t)bi * NTt * TDd + d] * w);
    }

    __shared__ double r0[THREADS], r1[THREADS], r2[THREADS], r3[THREADS];
    r0[tid] = seg; r1[tid] = lab; r2[tid] = vx; r3[tid] = hg;
    __syncthreads();
    #pragma unroll
    for (int off = THREADS / 2; off; off >>= 1) {
        if (tid < off) {
            r0[tid] += r0[tid + off];
            r1[tid] += r1[tid + off];
            r2[tid] += r2[tid + off];
            r3[tid] += r3[tid + off];
        }
        __syncthreads();
    }
    if (tid == 0) {
        const double seg_loss   = r0[0] / ((double)NHh * Bn);
        const double label_loss = r1[0] / ((double)Cc * Bn);
        const double vert_loss  = r2[0] / ((double)Bn * 3.0);
        const double hung_loss  = r3[0] / (double)Bn;
        out[0] = (float)(hung_loss + label_loss + vert_loss + seg_loss);
    }
}

extern "C" void kernel_launch(void* const* d_in, const int* in_sizes, int n_in,
                              void* d_out, int out_size)
{
    const float* pred_params     = (const float*)d_in[0];
    const float* pred_logits     = (const float*)d_in[1];
    const float* vertex          = (const float*)d_in[2];
    const float* hit_logits      = (const float*)d_in[3];
    const float* target_params   = (const float*)d_in[4];
    const void*  target_labels   = d_in[5];
    const void*  hit_labels      = d_in[6];
    const void*  preds_lengths   = d_in[7];
    const void*  targets_lengths = d_in[8];

    fused_kernel<<<Bn + SEG_BLOCKS, THREADS>>>(
        pred_params, hit_logits, target_params,
        target_labels, hit_labels, preds_lengths, targets_lengths);
    final_kernel<<<1, THREADS>>>(pred_logits, vertex, target_params, (float*)d_out);
}

// round 4
// speedup vs baseline: 1.1971x; 1.1971x over previous
#include <cuda_runtime.h>
#include <cstdint>

// Problem constants (from reference)
constexpr int Bn  = 64;      // batch
constexpr int Cc  = 32;      // preds per sample
constexpr int Pp  = 5;       // pred param dim
constexpr int TDd = 8;       // target param dim (use [3:8])
constexpr int NTt = 32;      // targets per sample
constexpr int NHh = 32768;   // hits
constexpr int SCc = 16;      // seg classes

constexpr int SEG_BLOCKS = 2048;
constexpr int THREADS    = 256;
constexpr int TOTAL_BLOCKS = SEG_BLOCKS + Bn;
constexpr long long TOTAL_ROWS = (long long)Bn * NHh;            // 2,097,152
constexpr long long STRIDE     = (long long)SEG_BLOCKS * THREADS; // 524,288
// 4 * STRIDE == TOTAL_ROWS exactly -> fully unrolled 4 rows/thread, no bounds checks
constexpr int ROWS_PER_THREAD = 4;

#define FULL 0xffffffffu

// Scratch (no device allocation allowed)
__device__ float        g_seg_partial[SEG_BLOCKS];
__device__ float        g_samp[Bn];          // per-sample hungarian + label contribution
__device__ double       g_vertex;            // vertex-loss sum (pre /192)
__device__ unsigned int g_counter = 0;       // arrival counter (self-resetting)

// ---- int32 / int64 input detection -----------------------------------------
// If the ints are true little-endian int64 (values in [0,16)), every odd 32-bit
// word of the first 32 elements is 0. With int32 data those words are iid
// uniform in [0,16): P(all 32 zero) = 16^-32.
__device__ __forceinline__ bool detect_int64(const void* hit_labels)
{
    const int* w = (const int*)hit_labels;
    int acc = 0;
    #pragma unroll
    for (int i = 0; i < 32; i++) acc |= w[2 * i + 1];
    return acc == 0;
}

__device__ __forceinline__ int geti(const void* p, long long i, bool i64)
{
    return i64 ? (int)((const long long*)p)[i] : ((const int*)p)[i];
}

// Select element `lab` (0..15) from 4 float4s without memory access (15 SELs).
__device__ __forceinline__ float select16(const float4& a, const float4& b,
                                          const float4& c, const float4& d, int lab)
{
    const bool b0 = lab & 1, b1 = lab & 2, b2 = lab & 4, b3 = lab & 8;
    const float p0 = b0 ? a.y : a.x, p1 = b0 ? a.w : a.z;
    const float p2 = b0 ? b.y : b.x, p3 = b0 ? b.w : b.z;
    const float p4 = b0 ? c.y : c.x, p5 = b0 ? c.w : c.z;
    const float p6 = b0 ? d.y : d.x, p7 = b0 ? d.w : d.z;
    const float q0 = b1 ? p1 : p0, q1 = b1 ? p3 : p2;
    const float q2 = b1 ? p5 : p4, q3 = b1 ? p7 : p6;
    const float r0 = b2 ? q1 : q0, r1 = b2 ? q3 : q2;
    return b3 ? r1 : r0;
}

__global__ void __launch_bounds__(THREADS)
fused_kernel(const float* __restrict__ pred_params,
             const float* __restrict__ pred_logits,
             const float* __restrict__ vertex,
             const float* __restrict__ hit_logits,
             const float* __restrict__ target_params,
             const void*  __restrict__ target_labels,
             const void*  __restrict__ hit_labels,
             const void*  __restrict__ preds_lengths,
             const void*  __restrict__ targets_lengths,
             float* __restrict__ out)
{
    const int tid = threadIdx.x;
    const bool i64 = detect_int64(hit_labels);

    __shared__ double cost[32 * 33];
    __shared__ double u_sh[33];
    __shared__ int    adj_sh[32];
    __shared__ float  red[THREADS];
    __shared__ bool   is_last;

    if (blockIdx.x < (unsigned)Bn) {
        // ====== Matching: replicate the reference's _lsa EXACTLY =================
        // (reference's minv/way updates are computed on copies and never written
        //  back: each inner step is a fresh argmin, assignment is single-step)
        const int b = blockIdx.x;

        const int n0 = geti(preds_lengths, b, i64);
        const int m0 = geti(targets_lengths, b, i64);
        const bool transposed = n0 > m0;   // reference transposes so rows <= cols
        const int n = transposed ? m0 : n0;
        const int m = transposed ? n0 : m0;

        const float* pp = pred_params   + (size_t)b * Cc * Pp;
        const float* tp = target_params + (size_t)b * NTt * TDd;

        // Fill full 32x32 cost in f64 (sequential 5-term sum, matches numpy)
        for (int idx = tid; idx < 32 * 32; idx += THREADS) {
            const int r = idx >> 5, c = idx & 31;
            const int pi = transposed ? c : r;
            const int ti = transposed ? r : c;
            double s = 0.0;
            #pragma unroll
            for (int d = 0; d < Pp; d++)
                s += fabs((double)pp[pi * Pp + d] - (double)tp[ti * TDd + 3 + d]);
            cost[r * 33 + c] = s;
        }
        if (tid < 33) u_sh[tid] = 0.0;
        __syncthreads();

        if (tid < 32) {
            const int lane = tid;
            const double INF = 1e300;
            double v = 0.0;             // column potential; lane owns column lane+1
            int p = 0;                  // row matched to this column (0 = none)

            for (int i = 1; i <= n; i++) {
                bool used = false;
                int j0 = 0;
                while (true) {
                    if (j0 > 0 && lane == j0 - 1) used = true;
                    const int i0 = (j0 == 0) ? i : __shfl_sync(FULL, p, j0 - 1);
                    const double ui0 = u_sh[i0];
                    double val = (lane < m && !used)
                               ? (cost[(i0 - 1) * 33 + lane] - ui0 - v) : INF;
                    int idx = lane;
                    #pragma unroll
                    for (int off = 16; off; off >>= 1) {
                        const double ov = __shfl_xor_sync(FULL, val, off);
                        const int    oi = __shfl_xor_sync(FULL, idx, off);
                        if (ov < val || (ov == val && oi < idx)) { val = ov; idx = oi; }
                    }
                    const double delta = val;
                    const int j1 = idx + 1;

                    if (lane == 0) u_sh[i] += delta;   // u[p[0]] = u[i] += delta
                    if (used) {                         // u[p[used]] += delta
                        u_sh[p] += delta;               // distinct rows: no race
                        v -= delta;                     // v[used]   -= delta
                    }
                    __syncwarp();
                    j0 = j1;
                    const int pj0 = __shfl_sync(FULL, p, j0 - 1);
                    if (pj0 == 0) break;
                }
                if (lane == j0 - 1) p = i;  // way[] stays 0 -> single-step assign
                __syncwarp();
            }

            // matched pairs: lane < m with p != 0 : alg_row = p-1, alg_col = lane
            const bool matched = (lane < m) && (p != 0);
            int pred_i = 0, tgt_i = 0;
            float l1 = 0.0f;
            if (matched) {
                pred_i = transposed ? lane : (p - 1);
                tgt_i  = transposed ? (p - 1) : lane;
                float s = 0.0f;
                #pragma unroll
                for (int d = 0; d < Pp; d++)
                    s += fabsf(pp[pred_i * Pp + d] - tp[tgt_i * TDd + 3 + d]);
                l1 = s;
            }
            float tot = l1;
            #pragma unroll
            for (int off = 16; off; off >>= 1) tot += __shfl_xor_sync(FULL, tot, off);

            // adjusted class targets (default 1, matched rows get target label)
            adj_sh[lane] = 1;
            __syncwarp();
            if (matched)
                adj_sh[pred_i] = geti(target_labels, (long long)b * NTt + tgt_i, i64);
            __syncwarp();

            // label NLL for this sample's 32 rows (lane = row)
            const float* x = pred_logits + ((size_t)b * Cc + lane) * 3;
            const float x0 = x[0], x1 = x[1], x2 = x[2];
            const float mx = fmaxf(x0, fmaxf(x1, x2));
            const float sm = __expf(x0 - mx) + __expf(x1 - mx) + __expf(x2 - mx);
            const int a = adj_sh[lane];
            const float xa = (a == 0) ? x0 : ((a == 1) ? x1 : x2);
            float nll = (mx + __logf(sm)) - xa;
            #pragma unroll
            for (int off = 16; off; off >>= 1) nll += __shfl_xor_sync(FULL, nll, off);

            if (lane == 0) {
                g_samp[b] = tot / (float)(n * Pp) + nll / (float)Cc;
                __threadfence();
            }
        } else if (b == 0 && tid < 64) {
            // ---- vertex loss (block 0, warp 1): 192 elements ----
            const int lane = tid - 32;
            double vx = 0.0;
            for (int e = lane; e < Bn * 3; e += 32) {
                const int bi = e / 3, d = e % 3;
                const float w = (d == 2) ? 0.8f : 0.1f;
                vx += (double)fabsf(vertex[e] * w
                                    - target_params[(size_t)bi * NTt * TDd + d] * w);
            }
            #pragma unroll
            for (int off = 16; off; off >>= 1)
                vx += __shfl_xor_sync(FULL, vx, off);
            if (lane == 0) { g_vertex = vx; __threadfence(); }
        }
        __syncthreads();
    } else {
        // ================= Segmentation loss scan (HBM-bound) =====================
        const int sb = blockIdx.x - Bn;
        const long long base = (long long)sb * THREADS + tid;

        float4 A[ROWS_PER_THREAD], B4[ROWS_PER_THREAD], C4[ROWS_PER_THREAD], D4[ROWS_PER_THREAD];
        int lab[ROWS_PER_THREAD];
        #pragma unroll
        for (int k = 0; k < ROWS_PER_THREAD; k++) {
            const long long row = base + (long long)k * STRIDE;
            const float4* p4 = (const float4*)(hit_logits + row * SCc);
            A[k] = p4[0]; B4[k] = p4[1]; C4[k] = p4[2]; D4[k] = p4[3];
            lab[k] = geti(hit_labels, row, i64);
        }
        float acc = 0.0f;
        #pragma unroll
        for (int k = 0; k < ROWS_PER_THREAD; k++) {
            const float4 a = A[k], b4 = B4[k], c = C4[k], d = D4[k];
            float mx = fmaxf(fmaxf(fmaxf(a.x, a.y), fmaxf(a.z, a.w)),
                             fmaxf(fmaxf(b4.x, b4.y), fmaxf(b4.z, b4.w)));
            mx = fmaxf(mx, fmaxf(fmaxf(c.x, c.y), fmaxf(c.z, c.w)));
            mx = fmaxf(mx, fmaxf(fmaxf(d.x, d.y), fmaxf(d.z, d.w)));
            float s = __expf(a.x - mx) + __expf(a.y - mx) + __expf(a.z - mx) + __expf(a.w - mx)
                    + __expf(b4.x - mx) + __expf(b4.y - mx) + __expf(b4.z - mx) + __expf(b4.w - mx)
                    + __expf(c.x - mx) + __expf(c.y - mx) + __expf(c.z - mx) + __expf(c.w - mx)
                    + __expf(d.x - mx) + __expf(d.y - mx) + __expf(d.z - mx) + __expf(d.w - mx);
            const float xl = select16(a, b4, c, d, lab[k]);
            acc += (mx + __logf(s)) - xl;
        }
        red[tid] = acc;
        __syncthreads();
        #pragma unroll
        for (int off = THREADS / 2; off; off >>= 1) {
            if (tid < off) red[tid] += red[tid + off];
            __syncthreads();
        }
        if (tid == 0) { g_seg_partial[sb] = red[0]; __threadfence(); }
        __syncthreads();
    }

    // ================= Last-block final reduction ================================
    if (tid == 0) {
        const unsigned old = atomicAdd(&g_counter, 1u);
        is_last = (old == (unsigned)(TOTAL_BLOCKS - 1));
    }
    __syncthreads();
    if (!is_last) return;
    __threadfence();   // acquire: all partials visible

    double seg = 0.0, smp = 0.0;
    for (int i = tid; i < SEG_BLOCKS; i += THREADS) seg += (double)g_seg_partial[i];
    for (int i = tid; i < Bn; i += THREADS)         smp += (double)g_samp[i];

    __shared__ double d0[THREADS], d1[THREADS];
    d0[tid] = seg; d1[tid] = smp;
    __syncthreads();
    #pragma unroll
    for (int off = THREADS / 2; off; off >>= 1) {
        if (tid < off) { d0[tid] += d0[tid + off]; d1[tid] += d1[tid + off]; }
        __syncthreads();
    }
    if (tid == 0) {
        const double seg_loss  = d0[0] / ((double)NHh * Bn);
        const double samp_loss = d1[0] / (double)Bn;       // hungarian + label
        const double vert_loss = g_vertex / ((double)Bn * 3.0);
        out[0] = (float)(samp_loss + vert_loss + seg_loss);
        g_counter = 0;          // reset for next graph replay
        __threadfence();
    }
}

extern "C" void kernel_launch(void* const* d_in, const int* in_sizes, int n_in,
                              void* d_out, int out_size)
{
    const float* pred_params     = (const float*)d_in[0];
    const float* pred_logits     = (const float*)d_in[1];
    const float* vertex          = (const float*)d_in[2];
    const float* hit_logits      = (const float*)d_in[3];
    const float* target_params   = (const float*)d_in[4];
    const void*  target_labels   = d_in[5];
    const void*  hit_labels      = d_in[6];
    const void*  preds_lengths   = d_in[7];
    const void*  targets_lengths = d_in[8];

    fused_kernel<<<TOTAL_BLOCKS, THREADS>>>(
        pred_params, pred_logits, vertex, hit_logits, target_params,
        target_labels, hit_labels, preds_lengths, targets_lengths,
        (float*)d_out);
}